// round 3
// baseline (speedup 1.0000x reference)
#include <cuda_runtime.h>
#include <cstdint>

#define BB 2
#define VV 5
#define CC 16
#define HH 512
#define WW 640
#define NN 131072
#define BV (BB*VV)
#define HW (HH*WW)

// Transpose geometry: 256 px per CTA, HW/256 = 1280 CTAs per bv slice (exact).
#define T_CTAS_PER_SLICE (HW/256)          // 1280
#define T_CTAS           (BV*T_CTAS_PER_SLICE)  // 12800
// Main geometry: 64 points per CTA (256 thr = 64 pts x 4 quad lanes)
#define M_CTAS_PER_SLICE (NN/64)           // 2048
#define M_CTAS           (BV*M_CTAS_PER_SLICE)  // 20480
#define TOTAL_CTAS       (T_CTAS + M_CTAS)

// Transposed feature maps: (BV, H, W, C) — all 16 channels of a pixel contiguous (64B).
__device__ float g_fmT[(size_t)BV * HW * CC];
// Per-slice completion counters for transpose -> main dependency.
__device__ int g_done[BV];

__global__ void fgf_init() {
    if (threadIdx.x < BV) g_done[threadIdx.x] = 0;
}

__device__ __forceinline__ float4 lerp4(float4 a, float4 b, float f) {
    float4 r;
    r.x = fmaf(f, b.x - a.x, a.x);
    r.y = fmaf(f, b.y - a.y, a.y);
    r.z = fmaf(f, b.z - a.z, a.z);
    r.w = fmaf(f, b.w - a.w, a.w);
    return r;
}

__global__ void __launch_bounds__(256)
fgf_fused(const float* __restrict__ fm,
          const float* __restrict__ pts,
          const float* __restrict__ Kmat,
          const float* __restrict__ Emat,
          float* __restrict__ out) {
    int bid = blockIdx.x;
    int tid = threadIdx.x;

    if (bid < T_CTAS) {
        // ---------------- transpose role: (BV,C,H,W) -> (BV,H,W,C) ----------
        int pix = bid * 256 + tid;
        int bv = pix / HW;
        int r  = pix - bv * HW;
        const float* src = fm + (size_t)bv * CC * HW + r;
        float v[CC];
#pragma unroll
        for (int c = 0; c < CC; c++) v[c] = src[(size_t)c * HW];
        float4* dst = reinterpret_cast<float4*>(g_fmT + ((size_t)bv * HW + r) * CC);
#pragma unroll
        for (int q = 0; q < 4; q++)
            dst[q] = make_float4(v[4*q], v[4*q+1], v[4*q+2], v[4*q+3]);

        __threadfence();
        __syncthreads();
        if (tid == 0) atomicAdd(&g_done[bv], 1);
        return;
    }

    // ---------------- main role: project + stencil bilinear ----------------
    int mid   = bid - T_CTAS;
    int bv    = mid / M_CTAS_PER_SLICE;        // slice-major ordering
    int chunk = mid - bv * M_CTAS_PER_SLICE;
    int n0    = chunk * 64;

    // Wait until this bv slice is fully transposed.
    if (tid == 0) {
        volatile int* dp = &g_done[bv];
        while (*dp < T_CTAS_PER_SLICE) __nanosleep(200);
        __threadfence();
    }
    __syncthreads();

    __shared__ float sf [CC][66];
    __shared__ float sgx[CC][66];
    __shared__ float sgy[CC][66];

    int p = tid >> 2;        // point within CTA (0..63)
    int q = tid & 3;         // channel quad (0..3)
    int b = bv / VV;
    int n = n0 + p;

    const float* Kp = Kmat + bv * 9;
    const float* Ep = Emat + bv * 12;

    float px = pts[((size_t)b * 3 + 0) * NN + n];
    float py = pts[((size_t)b * 3 + 1) * NN + n];
    float pz = pts[((size_t)b * 3 + 2) * NN + n];

    float tx = Ep[0] * px + Ep[1] * py + Ep[2]  * pz + Ep[3];
    float ty = Ep[4] * px + Ep[5] * py + Ep[6]  * pz + Ep[7];
    float tz = Ep[8] * px + Ep[9] * py + Ep[10] * pz + Ep[11];

    float inz = 1.0f / tz;
    float nx = tx * inz, ny = ty * inz;
    float u = Kp[0] * nx + Kp[1] * ny + Kp[2];
    float v = Kp[3] * nx + Kp[4] * ny + Kp[5];

    const float sx = 2.0f / (float)(WW - 1);
    const float sy = 2.0f / (float)(HH - 1);
    float gx = (u - 0.5f) * sx - 1.0f;
    float gy = (v - 0.5f) * sy - 1.0f;

    // Pixel-space coords for the 5 stencil samples (mirrors reference arithmetic)
    float ix  = ((gx + 1.0f)      * (float)WW - 1.0f) * 0.5f;
    float iy  = ((gy + 1.0f)      * (float)HH - 1.0f) * 0.5f;
    float ixl = ((gx - sx + 1.0f) * (float)WW - 1.0f) * 0.5f;
    float ixr = ((gx + sx + 1.0f) * (float)WW - 1.0f) * 0.5f;
    float iyt = ((gy - sy + 1.0f) * (float)HH - 1.0f) * 0.5f;
    float iyb = ((gy + sy + 1.0f) * (float)HH - 1.0f) * 0.5f;

    float x0f = floorf(ix), y0f = floorf(iy);
    int x0 = (int)x0f, y0 = (int)y0f;

    float fa  = ix  - x0f;
    float fb  = iy  - y0f;
    float fxl = ixl - x0f + 1.0f;   // frac of left sample rel. pixel x0-1
    float fxr = ixr - x0f - 1.0f;   // frac of right sample rel. pixel x0+1
    float fyt = iyt - y0f + 1.0f;   // frac of top sample rel. row y0-1
    float fyb = iyb - y0f - 1.0f;   // frac of bottom sample rel. row y0+1

    int cxm = max(x0 - 1, 0);
    int cx0 = min(max(x0,     0), WW - 1);
    int cx1 = min(max(x0 + 1, 0), WW - 1);
    int cx2 = min(x0 + 2, WW - 1);
    int rym = max(y0 - 1, 0);
    int ry0 = min(max(y0,     0), HH - 1);
    int ry1 = min(max(y0 + 1, 0), HH - 1);
    int ry2 = min(y0 + 2, HH - 1);

    const float4* base4 = reinterpret_cast<const float4*>(g_fmT) + (size_t)bv * HW * 4;
#define TAP(Y, X) __ldg(base4 + (((Y) * WW + (X)) * 4 + q))
    float4 A0 = TAP(ry0, cxm), A1 = TAP(ry0, cx0), A2 = TAP(ry0, cx1), A3 = TAP(ry0, cx2);
    float4 B0 = TAP(ry1, cxm), B1 = TAP(ry1, cx0), B2 = TAP(ry1, cx1), B3 = TAP(ry1, cx2);
    float4 T1 = TAP(rym, cx0), T2 = TAP(rym, cx1);
    float4 U1 = TAP(ry2, cx0), U2 = TAP(ry2, cx1);
#undef TAP

    // Separable bilinear: x-lerps per row, then y-lerps
    float4 aL = lerp4(A0, A1, fxl);
    float4 aC = lerp4(A1, A2, fa);
    float4 aR = lerp4(A2, A3, fxr);
    float4 bL = lerp4(B0, B1, fxl);
    float4 bC = lerp4(B1, B2, fa);
    float4 bR = lerp4(B2, B3, fxr);
    float4 tC = lerp4(T1, T2, fa);
    float4 uC = lerp4(U1, U2, fa);

    float4 fC = lerp4(aC, bC, fb);
    float4 fL = lerp4(aL, bL, fb);
    float4 fR = lerp4(aR, bR, fb);
    float4 fT = lerp4(tC, aC, fyt);
    float4 fB = lerp4(bC, uC, fyb);

    int c0 = 4 * q;
    sf [c0+0][p] = fC.x;  sf [c0+1][p] = fC.y;  sf [c0+2][p] = fC.z;  sf [c0+3][p] = fC.w;
    sgx[c0+0][p] = 0.5f*(fR.x - fL.x);  sgy[c0+0][p] = 0.5f*(fB.x - fT.x);
    sgx[c0+1][p] = 0.5f*(fR.y - fL.y);  sgy[c0+1][p] = 0.5f*(fB.y - fT.y);
    sgx[c0+2][p] = 0.5f*(fR.z - fL.z);  sgy[c0+2][p] = 0.5f*(fB.z - fT.z);
    sgx[c0+3][p] = 0.5f*(fR.w - fL.w);  sgy[c0+3][p] = 0.5f*(fB.w - fT.w);

    __syncthreads();

    // Coalesced output: each warp writes 32 consecutive n of one channel.
    float*  fout = out;
    float2* gout = reinterpret_cast<float2*>(out + (size_t)BV * CC * NN);
    int i  = tid & 63;
    int cb = tid >> 6;       // 0..3
#pragma unroll
    for (int it = 0; it < 4; it++) {
        int c = it * 4 + cb;
        size_t o = ((size_t)bv * CC + c) * NN + n0 + i;
        fout[o] = sf[c][i];
        gout[o] = make_float2(sgx[c][i], sgy[c][i]);
    }
}

// ---------------------------------------------------------------------------
extern "C" void kernel_launch(void* const* d_in, const int* in_sizes, int n_in,
                              void* d_out, int out_size) {
    const float* fm  = (const float*)d_in[0];  // (B,V,C,H,W)
    const float* pts = (const float*)d_in[1];  // (B,3,N)
    const float* Km  = (const float*)d_in[2];  // (B,V,3,3)
    const float* Em  = (const float*)d_in[3];  // (B,V,3,4)
    float* out = (float*)d_out;                // f (B,V,C,N) ++ f_grad (B,V,C,N,2)

    fgf_init<<<1, 32>>>();
    fgf_fused<<<TOTAL_CTAS, 256>>>(fm, pts, Km, Em, out);
}

// round 4
// speedup vs baseline: 1.5279x; 1.5279x over previous
#include <cuda_runtime.h>
#include <cuda_fp16.h>
#include <cstdint>

#define BB 2
#define VV 5
#define CC 16
#define HH 512
#define WW 640
#define NN 131072
#define BV (BB*VV)
#define HW (HH*WW)

// Transposed feature maps in fp16: (BV, H, W, C) — 16 channels of a pixel = 32B.
__device__ __half g_fmT[(size_t)BV * HW * CC];

// ---------------------------------------------------------------------------
// Kernel 1: transpose + downconvert (BV, C, H, W) fp32 -> (BV, H, W, C) fp16
// ---------------------------------------------------------------------------
__global__ void fgf_transpose(const float* __restrict__ fm) {
    int pix = blockIdx.x * blockDim.x + threadIdx.x;
    if (pix >= BV * HW) return;
    int bv = pix / HW;
    int r  = pix - bv * HW;
    const float* src = fm + (size_t)bv * CC * HW + r;
    float v[CC];
#pragma unroll
    for (int c = 0; c < CC; c++) v[c] = src[(size_t)c * HW];

    __half2 h[8];
#pragma unroll
    for (int i = 0; i < 8; i++) h[i] = __floats2half2_rn(v[2*i], v[2*i+1]);

    uint4* dst = reinterpret_cast<uint4*>(g_fmT + ((size_t)bv * HW + r) * CC);
    const uint4* hs = reinterpret_cast<const uint4*>(h);
    dst[0] = hs[0];
    dst[1] = hs[1];
}

// ---------------------------------------------------------------------------
// Kernel 2: project + 5-point stencil bilinear on a shared 12-tap cross.
// Block = 128 threads = 32 points x 4 channel-quad lanes (8B fp16 per tap/lane).
// ---------------------------------------------------------------------------
__device__ __forceinline__ float4 lerp4(float4 a, float4 b, float f) {
    float4 r;
    r.x = fmaf(f, b.x - a.x, a.x);
    r.y = fmaf(f, b.y - a.y, a.y);
    r.z = fmaf(f, b.z - a.z, a.z);
    r.w = fmaf(f, b.w - a.w, a.w);
    return r;
}

__device__ __forceinline__ float4 load_tap(const uint2* __restrict__ base, int pix, int q) {
    uint2 raw = __ldg(base + pix * 4 + q);   // 8 bytes = 4 halfs
    __half2 h0 = *reinterpret_cast<__half2*>(&raw.x);
    __half2 h1 = *reinterpret_cast<__half2*>(&raw.y);
    float2 a = __half22float2(h0);
    float2 b = __half22float2(h1);
    return make_float4(a.x, a.y, b.x, b.y);
}

__global__ void __launch_bounds__(128)
fgf_main(const float* __restrict__ pts,
         const float* __restrict__ Kmat,
         const float* __restrict__ Emat,
         float* __restrict__ out) {
    __shared__ float sf [CC][34];
    __shared__ float sgx[CC][34];
    __shared__ float sgy[CC][34];

    int tid = threadIdx.x;
    int p   = tid >> 2;        // point within block (0..31)
    int q   = tid & 3;         // channel quad (0..3)
    int bv  = blockIdx.y;
    int b   = bv / VV;
    int n   = blockIdx.x * 32 + p;

    const float* Kp = Kmat + bv * 9;
    const float* Ep = Emat + bv * 12;

    float px = pts[((size_t)b * 3 + 0) * NN + n];
    float py = pts[((size_t)b * 3 + 1) * NN + n];
    float pz = pts[((size_t)b * 3 + 2) * NN + n];

    float tx = Ep[0] * px + Ep[1] * py + Ep[2]  * pz + Ep[3];
    float ty = Ep[4] * px + Ep[5] * py + Ep[6]  * pz + Ep[7];
    float tz = Ep[8] * px + Ep[9] * py + Ep[10] * pz + Ep[11];

    float inz = 1.0f / tz;
    float nx = tx * inz, ny = ty * inz;
    float u = Kp[0] * nx + Kp[1] * ny + Kp[2];
    float v = Kp[3] * nx + Kp[4] * ny + Kp[5];

    const float sx = 2.0f / (float)(WW - 1);
    const float sy = 2.0f / (float)(HH - 1);
    float gx = (u - 0.5f) * sx - 1.0f;
    float gy = (v - 0.5f) * sy - 1.0f;

    // Pixel-space coords for the 5 stencil samples (mirrors reference arithmetic)
    float ix  = ((gx + 1.0f)      * (float)WW - 1.0f) * 0.5f;
    float iy  = ((gy + 1.0f)      * (float)HH - 1.0f) * 0.5f;
    float ixl = ((gx - sx + 1.0f) * (float)WW - 1.0f) * 0.5f;
    float ixr = ((gx + sx + 1.0f) * (float)WW - 1.0f) * 0.5f;
    float iyt = ((gy - sy + 1.0f) * (float)HH - 1.0f) * 0.5f;
    float iyb = ((gy + sy + 1.0f) * (float)HH - 1.0f) * 0.5f;

    float x0f = floorf(ix), y0f = floorf(iy);
    int x0 = (int)x0f, y0 = (int)y0f;

    float fa  = ix  - x0f;
    float fb  = iy  - y0f;
    float fxl = ixl - x0f + 1.0f;   // left sample frac rel. pixel x0-1
    float fxr = ixr - x0f - 1.0f;   // right sample frac rel. pixel x0+1
    float fyt = iyt - y0f + 1.0f;   // top sample frac rel. row y0-1
    float fyb = iyb - y0f - 1.0f;   // bottom sample frac rel. row y0+2

    int cxm = max(x0 - 1, 0);
    int cx0 = min(max(x0,     0), WW - 1);
    int cx1 = min(max(x0 + 1, 0), WW - 1);
    int cx2 = min(x0 + 2, WW - 1);
    int rym = max(y0 - 1, 0);
    int ry0 = min(max(y0,     0), HH - 1);
    int ry1 = min(max(y0 + 1, 0), HH - 1);
    int ry2 = min(y0 + 2, HH - 1);

    const uint2* base = reinterpret_cast<const uint2*>(g_fmT) + (size_t)bv * HW * 4;
#define TAP(Y, X) load_tap(base, (Y) * WW + (X), q)
    float4 A0 = TAP(ry0, cxm), A1 = TAP(ry0, cx0), A2 = TAP(ry0, cx1), A3 = TAP(ry0, cx2);
    float4 B0 = TAP(ry1, cxm), B1 = TAP(ry1, cx0), B2 = TAP(ry1, cx1), B3 = TAP(ry1, cx2);
    float4 T1 = TAP(rym, cx0), T2 = TAP(rym, cx1);
    float4 U1 = TAP(ry2, cx0), U2 = TAP(ry2, cx1);
#undef TAP

    // Separable bilinear: x-lerps per row, then y-lerps
    float4 aL = lerp4(A0, A1, fxl);
    float4 aC = lerp4(A1, A2, fa);
    float4 aR = lerp4(A2, A3, fxr);
    float4 bL = lerp4(B0, B1, fxl);
    float4 bC = lerp4(B1, B2, fa);
    float4 bR = lerp4(B2, B3, fxr);
    float4 tC = lerp4(T1, T2, fa);
    float4 uC = lerp4(U1, U2, fa);

    float4 fC = lerp4(aC, bC, fb);
    float4 fL = lerp4(aL, bL, fb);
    float4 fR = lerp4(aR, bR, fb);
    float4 fT = lerp4(tC, aC, fyt);
    float4 fB = lerp4(bC, uC, fyb);

    int c0 = 4 * q;
    sf [c0+0][p] = fC.x;  sf [c0+1][p] = fC.y;  sf [c0+2][p] = fC.z;  sf [c0+3][p] = fC.w;
    sgx[c0+0][p] = 0.5f*(fR.x - fL.x);  sgy[c0+0][p] = 0.5f*(fB.x - fT.x);
    sgx[c0+1][p] = 0.5f*(fR.y - fL.y);  sgy[c0+1][p] = 0.5f*(fB.y - fT.y);
    sgx[c0+2][p] = 0.5f*(fR.z - fL.z);  sgy[c0+2][p] = 0.5f*(fB.z - fT.z);
    sgx[c0+3][p] = 0.5f*(fR.w - fL.w);  sgy[c0+3][p] = 0.5f*(fB.w - fT.w);

    __syncthreads();

    // Coalesced output: each warp writes 32 consecutive n of one channel.
    float*  fout = out;
    float2* gout = reinterpret_cast<float2*>(out + (size_t)BV * CC * NN);
    int wp = tid & 31;
    int cb = tid >> 5;          // 0..3
    size_t nb = (size_t)blockIdx.x * 32 + wp;
#pragma unroll
    for (int it = 0; it < 4; it++) {
        int c = it * 4 + cb;
        size_t o = ((size_t)bv * CC + c) * NN + nb;
        fout[o] = sf[c][wp];
        gout[o] = make_float2(sgx[c][wp], sgy[c][wp]);
    }
}

// ---------------------------------------------------------------------------
extern "C" void kernel_launch(void* const* d_in, const int* in_sizes, int n_in,
                              void* d_out, int out_size) {
    const float* fm  = (const float*)d_in[0];  // (B,V,C,H,W)
    const float* pts = (const float*)d_in[1];  // (B,3,N)
    const float* Km  = (const float*)d_in[2];  // (B,V,3,3)
    const float* Em  = (const float*)d_in[3];  // (B,V,3,4)
    float* out = (float*)d_out;                // f (B,V,C,N) ++ f_grad (B,V,C,N,2)

    {
        int total = BV * HW;
        int threads = 256;
        fgf_transpose<<<(total + threads - 1) / threads, threads>>>(fm);
    }
    {
        dim3 grid(NN / 32, BV);
        fgf_main<<<grid, 128>>>(pts, Km, Em, out);
    }
}